// round 15
// baseline (speedup 1.0000x reference)
#include <cuda_runtime.h>
#include <cuda_fp16.h>
#include <math.h>

#define N_TOK 4301
#define NP    4201
#define ND    100
#define D     768
#define H     12
#define HD    64
// attention scores are produced in log2 domain: fold log2(e) into q scale
#define QSCALE_LOG2 (0.125f * 1.4426950408889634f)
#define WSZ   (D * D)

// Scratch (allocation-free rule: __device__ globals)
__device__ __half g_xh[(size_t)N_TOK * D];
__device__ __half g_wh[(size_t)8 * WSZ];     // 0=wq_p 1=wq_d 2=wk_p 3=wk_d 4=wv_p 5=wv_d 6=wo_p 7=wo_d
__device__ __half g_q[(size_t)N_TOK * D];
__device__ __half g_k[(size_t)N_TOK * D];
__device__ __half g_v[(size_t)N_TOK * D];
__device__ float  g_o[(size_t)N_TOK * D];
__device__ __half g_oh[(size_t)N_TOK * D];

// ---------------------------------------------------------------------------
// helpers
// ---------------------------------------------------------------------------
__device__ __forceinline__ void mma_f16(float* c,
    unsigned a0, unsigned a1, unsigned a2, unsigned a3,
    unsigned b0, unsigned b1)
{
    asm volatile(
        "mma.sync.aligned.m16n8k16.row.col.f32.f16.f16.f32 "
        "{%0,%1,%2,%3}, {%4,%5,%6,%7}, {%8,%9}, {%0,%1,%2,%3};"
        : "+f"(c[0]), "+f"(c[1]), "+f"(c[2]), "+f"(c[3])
        : "r"(a0), "r"(a1), "r"(a2), "r"(a3), "r"(b0), "r"(b1));
}
__device__ __forceinline__ void ldsm_x4(unsigned& r0, unsigned& r1,
                                        unsigned& r2, unsigned& r3, unsigned addr)
{
    asm volatile("ldmatrix.sync.aligned.m8n8.x4.shared.b16 {%0,%1,%2,%3}, [%4];"
                 : "=r"(r0), "=r"(r1), "=r"(r2), "=r"(r3) : "r"(addr));
}
__device__ __forceinline__ void ldsm_x4_t(unsigned& r0, unsigned& r1,
                                          unsigned& r2, unsigned& r3, unsigned addr)
{
    asm volatile("ldmatrix.sync.aligned.m8n8.x4.trans.shared.b16 {%0,%1,%2,%3}, [%4];"
                 : "=r"(r0), "=r"(r1), "=r"(r2), "=r"(r3) : "r"(addr));
}
__device__ __forceinline__ unsigned packh2(float lo, float hi) {
    __half2 h = __floats2half2_rn(lo, hi);
    return *(unsigned*)&h;
}
__device__ __forceinline__ unsigned ex2h2(unsigned x) {
    unsigned r;
    asm("ex2.approx.f16x2 %0, %1;" : "=r"(r) : "r"(x));
    return r;
}
__device__ __forceinline__ void cp_async16(unsigned dst, const void* src, int srcsize) {
    asm volatile("cp.async.cg.shared.global [%0], [%1], 16, %2;"
                 :: "r"(dst), "l"(src), "r"(srcsize));
}
__device__ __forceinline__ void cp_commit() {
    asm volatile("cp.async.commit_group;");
}

// ---------------------------------------------------------------------------
// fp32 -> fp16 conversion pre-passes
// ---------------------------------------------------------------------------
__global__ void __launch_bounds__(256) f2h_x(
    const float* __restrict__ src, __half* __restrict__ dst, int n)
{
    int i = (blockIdx.x * 256 + threadIdx.x) * 8;
    if (i < n) {
        float4 v0 = *(const float4*)(src + i);
        float4 v1 = *(const float4*)(src + i + 4);
        __half2 h[4];
        h[0] = __floats2half2_rn(v0.x, v0.y);
        h[1] = __floats2half2_rn(v0.z, v0.w);
        h[2] = __floats2half2_rn(v1.x, v1.y);
        h[3] = __floats2half2_rn(v1.z, v1.w);
        *(uint4*)(dst + i) = *(uint4*)h;
    }
}

__global__ void __launch_bounds__(256) w2h(
    const float* __restrict__ w0, const float* __restrict__ w1,
    const float* __restrict__ w2, const float* __restrict__ w3,
    const float* __restrict__ w4, const float* __restrict__ w5,
    const float* __restrict__ w6, const float* __restrict__ w7,
    __half* __restrict__ dst)
{
    const float* src;
    switch (blockIdx.y) {
        case 0: src = w0; break; case 1: src = w1; break;
        case 2: src = w2; break; case 3: src = w3; break;
        case 4: src = w4; break; case 5: src = w5; break;
        case 6: src = w6; break; default: src = w7; break;
    }
    __half* d = dst + (size_t)blockIdx.y * WSZ;
    int i = (blockIdx.x * 256 + threadIdx.x) * 8;
    float4 v0 = *(const float4*)(src + i);
    float4 v1 = *(const float4*)(src + i + 4);
    __half2 h[4];
    h[0] = __floats2half2_rn(v0.x, v0.y);
    h[1] = __floats2half2_rn(v0.z, v0.w);
    h[2] = __floats2half2_rn(v1.x, v1.y);
    h[3] = __floats2half2_rn(v1.z, v1.w);
    *(uint4*)(d + i) = *(uint4*)h;
}

// ---------------------------------------------------------------------------
// fp16 GEMM tile body (R13, unchanged): C = (A @ W^T + bias) * scale
// ---------------------------------------------------------------------------
#define GNK (D / 32)
#define HS  40

struct GemmSmemH {
    __half A[2][128 * HS];
    __half B[2][128 * HS];
};

template <bool HALF_OUT>
__device__ __forceinline__ void gemm_body_h(
    const __half* __restrict__ A, const __half* __restrict__ W,
    const float* __restrict__ bias,
    float* __restrict__ Cf, __half* __restrict__ Ch,
    int m0, int n0, int M, float scale, GemmSmemH& s)
{
    const int tid = threadIdx.x;
    const int w = tid >> 5;
    const int l = tid & 31;
    const int g = l >> 2;
    const int t = l & 3;
    const int wm = (w >> 2) * 64;
    const int wn = (w & 3) * 32;

    int cr[2], cc[2];
#pragma unroll
    for (int it = 0; it < 2; it++) {
        int slot = tid + 256 * it;
        cr[it] = slot >> 2;
        cc[it] = (slot & 3) * 8;
    }
    unsigned au = (unsigned)__cvta_generic_to_shared(s.A);
    unsigned bu = (unsigned)__cvta_generic_to_shared(s.B);

#pragma unroll
    for (int it = 0; it < 2; it++) {
        int row = m0 + cr[it];
        int ok = (row < M) ? 16 : 0;
        cp_async16(au + (cr[it] * HS + cc[it]) * 2,
                   A + (size_t)(ok ? row : m0) * D + cc[it], ok);
        cp_async16(bu + (cr[it] * HS + cc[it]) * 2,
                   W + (size_t)(n0 + cr[it]) * D + cc[it], 16);
    }
    cp_commit();

    float acc[4][4][4];
#pragma unroll
    for (int i = 0; i < 4; i++)
#pragma unroll
        for (int j = 0; j < 4; j++)
#pragma unroll
            for (int r = 0; r < 4; r++) acc[i][j][r] = 0.f;

    const int la = (l & 15) * HS + ((l >> 4) & 1) * 8;
    const int lb = (((l >> 4) << 3) + (l & 7)) * HS + ((l >> 3) & 1) * 8;

    for (int ki = 0; ki < GNK; ki++) {
        asm volatile("cp.async.wait_group 0;");
        __syncthreads();
        const int buf = ki & 1;

        if (ki + 1 < GNK) {
            const int k0 = (ki + 1) * 32;
            const unsigned an = au + ((buf ^ 1) * 128 * HS) * 2;
            const unsigned bn = bu + ((buf ^ 1) * 128 * HS) * 2;
#pragma unroll
            for (int it = 0; it < 2; it++) {
                int row = m0 + cr[it];
                int ok = (row < M) ? 16 : 0;
                cp_async16(an + (cr[it] * HS + cc[it]) * 2,
                           A + (size_t)(ok ? row : m0) * D + k0 + cc[it], ok);
                cp_async16(bn + (cr[it] * HS + cc[it]) * 2,
                           W + (size_t)(n0 + cr[it]) * D + k0 + cc[it], 16);
            }
            cp_commit();
        }

        const unsigned ab = au + (buf * 128 * HS) * 2;
        const unsigned bb = bu + (buf * 128 * HS) * 2;
#pragma unroll
        for (int kk = 0; kk < 2; kk++) {
            unsigned a[4][4];
#pragma unroll
            for (int i = 0; i < 4; i++)
                ldsm_x4(a[i][0], a[i][1], a[i][2], a[i][3],
                        ab + ((wm + i * 16) * HS + kk * 16 + la) * 2);
#pragma unroll
            for (int j2 = 0; j2 < 2; j2++) {
                unsigned b0, b1, b2, b3;
                ldsm_x4(b0, b1, b2, b3,
                        bb + ((wn + j2 * 16) * HS + kk * 16 + lb) * 2);
#pragma unroll
                for (int i = 0; i < 4; i++) {
                    mma_f16(acc[i][2 * j2],     a[i][0], a[i][1], a[i][2], a[i][3], b0, b1);
                    mma_f16(acc[i][2 * j2 + 1], a[i][0], a[i][1], a[i][2], a[i][3], b2, b3);
                }
            }
        }
        __syncthreads();
    }

#pragma unroll
    for (int j = 0; j < 4; j++) {
        int c0 = n0 + wn + j * 8 + t * 2;
        float b0v = bias ? bias[c0] : 0.f;
        float b1v = bias ? bias[c0 + 1] : 0.f;
#pragma unroll
        for (int i = 0; i < 4; i++) {
            int r0 = m0 + wm + i * 16 + g;
            int r1 = r0 + 8;
            if (r0 < M) {
                float px = (acc[i][j][0] + b0v) * scale;
                float py = (acc[i][j][1] + b1v) * scale;
                if (HALF_OUT)
                    *(__half2*)(Ch + (size_t)r0 * D + c0) = __floats2half2_rn(px, py);
                else
                    *(float2*)(Cf + (size_t)r0 * D + c0) = make_float2(px, py);
            }
            if (r1 < M) {
                float px = (acc[i][j][2] + b0v) * scale;
                float py = (acc[i][j][3] + b1v) * scale;
                if (HALF_OUT)
                    *(__half2*)(Ch + (size_t)r1 * D + c0) = __floats2half2_rn(px, py);
                else
                    *(float2*)(Cf + (size_t)r1 * D + c0) = make_float2(px, py);
            }
        }
    }
}

// Fused QKV: grid (6, 34, 3). q is scaled into the log2 domain.
__global__ void __launch_bounds__(256, 2) qkv_gemm(
    const __half* __restrict__ x, const __half* __restrict__ wh,
    const float* __restrict__ bq_p, const float* __restrict__ bq_d,
    const float* __restrict__ bv_p, const float* __restrict__ bv_d,
    __half* __restrict__ q, __half* __restrict__ k, __half* __restrict__ v)
{
    __shared__ GemmSmemH s;
    const bool det = (blockIdx.y == gridDim.y - 1);
    const int m0 = det ? NP : blockIdx.y * 128;
    const int M  = det ? N_TOK : NP;
    const int z = blockIdx.z;

    int wsel;
    const float* bias;
    __half* C;
    float scale = 1.f;
    if (z == 0) {
        wsel = det ? 1 : 0; bias = det ? bq_d : bq_p; C = q; scale = QSCALE_LOG2;
    } else if (z == 1) {
        wsel = det ? 3 : 2; bias = nullptr; C = k;
    } else {
        wsel = det ? 5 : 4; bias = det ? bv_d : bv_p; C = v;
    }
    gemm_body_h<true>(x, wh + (size_t)wsel * WSZ, bias, nullptr, C,
                      m0, blockIdx.x * 128, M, scale, s);
}

__global__ void __launch_bounds__(256, 2) out_gemm(
    const __half* __restrict__ A, const __half* __restrict__ wh,
    const float* __restrict__ bo_p, const float* __restrict__ bo_d,
    float* __restrict__ C)
{
    __shared__ GemmSmemH s;
    const bool det = (blockIdx.y == gridDim.y - 1);
    const int m0 = det ? NP : blockIdx.y * 128;
    const int M  = det ? N_TOK : NP;
    gemm_body_h<false>(A, wh + (size_t)(det ? 7 : 6) * WSZ,
                       det ? bo_d : bo_p, C, nullptr,
                       m0, blockIdx.x * 128, M, 1.f, s);
}

// ---------------------------------------------------------------------------
// fp16 flash attention, max-free exp2 softmax.
// Scores arrive in log2 domain (q pre-scaled). P = ex2.approx.f16x2(s) is
// directly the PV A-fragment. Row sums l via a ones-column mma. K and V both
// double-buffered -> ONE barrier per tile.
// ---------------------------------------------------------------------------
#define KH 72
#define VH 72
#define NKT ((N_TOK + 63) / 64)
#define ATT_SMEM ((2 * 64 * KH + 2 * 64 * VH) * 2)

__global__ void __launch_bounds__(256, 2) attn_tc(
    const __half* __restrict__ q, const __half* __restrict__ k,
    const __half* __restrict__ v, float* __restrict__ o)
{
    extern __shared__ __half smh[];
    __half* Ks0 = smh;                   // [2][64][KH]
    __half* Vs0 = smh + 2 * 64 * KH;     // [2][64][VH]

    const int h = blockIdx.y;
    const int q0 = blockIdx.x * 128;
    const int tid = threadIdx.x;
    const int w = tid >> 5;
    const int l = tid & 31;
    const int g = l >> 2;
    const int t = l & 3;
    const int wq = w * 16;
    const size_t hoff = (size_t)h * HD;
    const unsigned ONE2 = 0x3C003C00u;   // half2(1, 1)

    int cr_[2], cc_[2];
#pragma unroll
    for (int it = 0; it < 2; it++) {
        int slot = tid + 256 * it;
        cr_[it] = slot >> 3;
        cc_[it] = (slot & 7) * 8;
    }
    unsigned ks_u = (unsigned)__cvta_generic_to_shared(Ks0);
    unsigned vs_u = (unsigned)__cvta_generic_to_shared(Vs0);

    // prefetch tile 0 into buffer 0
#pragma unroll
    for (int it = 0; it < 2; it++) {
        cp_async16(ks_u + (cr_[it] * KH + cc_[it]) * 2,
                   k + (size_t)cr_[it] * D + hoff + cc_[it], 16);
        cp_async16(vs_u + (cr_[it] * VH + cc_[it]) * 2,
                   v + (size_t)cr_[it] * D + hoff + cc_[it], 16);
    }
    cp_commit();

    // Q a-frags in registers
    unsigned aq[4][4];
    {
        int gr0 = q0 + wq + g, gr1 = gr0 + 8;
        bool v0 = gr0 < N_TOK, v1 = gr1 < N_TOK;
        const __half* q0p = q + (size_t)gr0 * D + hoff;
        const __half* q1p = q + (size_t)gr1 * D + hoff;
#pragma unroll
        for (int s = 0; s < 4; s++) {
            int c0 = s * 16 + 2 * t;
            aq[s][0] = v0 ? *(const unsigned*)(q0p + c0) : 0u;
            aq[s][1] = v1 ? *(const unsigned*)(q1p + c0) : 0u;
            aq[s][2] = v0 ? *(const unsigned*)(q0p + c0 + 8) : 0u;
            aq[s][3] = v1 ? *(const unsigned*)(q1p + c0 + 8) : 0u;
        }
    }

    const int lk = (((l >> 4) << 3) + (l & 7)) * KH + ((l >> 3) & 1) * 8;
    const int lv = ((((l >> 3) & 1) << 3) + (l & 7)) * VH + ((l >> 4) << 3);

    float oacc[8][4];
#pragma unroll
    for (int n = 0; n < 8; n++)
#pragma unroll
        for (int r = 0; r < 4; r++) oacc[n][r] = 0.f;
    float lacc[4] = { 0.f, 0.f, 0.f, 0.f };

    for (int ti = 0; ti < NKT; ti++) {
        const int t0 = ti * 64;
        const int cnt = min(64, N_TOK - t0);
        const int buf = ti & 1;
        const unsigned kb_u = ks_u + buf * 64 * KH * 2;
        const unsigned vb_u = vs_u + buf * 64 * VH * 2;

        asm volatile("cp.async.wait_group 0;");
        __syncthreads();   // single barrier per tile

        // prefetch tile ti+1 into buf^1 (both K and V double-buffered)
        if (ti + 1 < NKT) {
            const int nt0 = t0 + 64;
            const int ncnt = min(64, N_TOK - nt0);
            const unsigned kn = ks_u + (buf ^ 1) * 64 * KH * 2;
            const unsigned vn = vs_u + (buf ^ 1) * 64 * VH * 2;
#pragma unroll
            for (int it = 0; it < 2; it++) {
                int row = cr_[it], cc = cc_[it];
                int ok = (row < ncnt) ? 16 : 0;
                size_t off = (size_t)(nt0 + (ok ? row : 0)) * D + hoff + cc;
                cp_async16(kn + (row * KH + cc) * 2, k + off, ok);
                cp_async16(vn + (row * VH + cc) * 2, v + off, ok);
            }
            cp_commit();
        }

        // S = Q @ K^T (log2-domain scores, fp32 accum)
        float sc[8][4];
#pragma unroll
        for (int n = 0; n < 8; n++)
#pragma unroll
            for (int r = 0; r < 4; r++) sc[n][r] = 0.f;

#pragma unroll
        for (int s = 0; s < 4; s++) {
#pragma unroll
            for (int np = 0; np < 4; np++) {
                unsigned b0, b1, b2, b3;
                ldsm_x4(b0, b1, b2, b3,
                        kb_u + (np * 16 * KH + s * 16 + lk) * 2);
                mma_f16(sc[2 * np],     aq[s][0], aq[s][1], aq[s][2], aq[s][3], b0, b1);
                mma_f16(sc[2 * np + 1], aq[s][0], aq[s][1], aq[s][2], aq[s][3], b2, b3);
            }
        }

        // Mask padded keys (last tile only): exp2(-60) == 0
        if (cnt < 64) {
#pragma unroll
            for (int n = 0; n < 8; n++) {
                int j0 = n * 8 + t * 2;
                if (j0 >= cnt)     { sc[n][0] = -60.f; sc[n][2] = -60.f; }
                if (j0 + 1 >= cnt) { sc[n][1] = -60.f; sc[n][3] = -60.f; }
            }
        }

        // P = exp2(S) in fp16 (directly PV a-frags); l += P @ 1 via mma
#pragma unroll
        for (int s = 0; s < 4; s++) {
            unsigned a0 = ex2h2(packh2(sc[2 * s][0],     sc[2 * s][1]));
            unsigned a1 = ex2h2(packh2(sc[2 * s][2],     sc[2 * s][3]));
            unsigned a2 = ex2h2(packh2(sc[2 * s + 1][0], sc[2 * s + 1][1]));
            unsigned a3 = ex2h2(packh2(sc[2 * s + 1][2], sc[2 * s + 1][3]));
            mma_f16(lacc, a0, a1, a2, a3, ONE2, ONE2);
#pragma unroll
            for (int np = 0; np < 4; np++) {
                unsigned b0, b1, b2, b3;
                ldsm_x4_t(b0, b1, b2, b3,
                          vb_u + (s * 16 * VH + np * 16 + lv) * 2);
                mma_f16(oacc[2 * np],     a0, a1, a2, a3, b0, b1);
                mma_f16(oacc[2 * np + 1], a0, a1, a2, a3, b2, b3);
            }
        }
    }

    // Epilogue: l0 = lacc[0] (row g), l1 = lacc[2] (row g+8)
    float i0 = 1.f / lacc[0], i1 = 1.f / lacc[2];
    int gr0 = q0 + wq + g, gr1 = gr0 + 8;
#pragma unroll
    for (int n = 0; n < 8; n++) {
        int c = h * HD + n * 8 + t * 2;
        if (gr0 < N_TOK) {
            float2 p;
            p.x = oacc[n][0] * i0; p.y = oacc[n][1] * i0;
            *(float2*)(o + (size_t)gr0 * D + c) = p;
        }
        if (gr1 < N_TOK) {
            float2 p;
            p.x = oacc[n][2] * i1; p.y = oacc[n][3] * i1;
            *(float2*)(o + (size_t)gr1 * D + c) = p;
        }
    }
}

// ---------------------------------------------------------------------------
// LayerNorm: reads fp32 attention output, writes fp16 for the out-projection.
// ---------------------------------------------------------------------------
__global__ void __launch_bounds__(256) ln_kernel(
    const float* __restrict__ o, __half* __restrict__ oh,
    const float* __restrict__ g, const float* __restrict__ b)
{
    const int row = blockIdx.x;
    const float* p = o + (size_t)row * D;
    __half* ph = oh + (size_t)row * D;
    const int t = threadIdx.x;
    float x0 = p[t], x1 = p[t + 256], x2 = p[t + 512];
    float s = x0 + x1 + x2;
    float sq = x0 * x0 + x1 * x1 + x2 * x2;

    __shared__ float red[64];
#pragma unroll
    for (int off = 16; off > 0; off >>= 1) {
        s  += __shfl_down_sync(0xffffffffu, s, off);
        sq += __shfl_down_sync(0xffffffffu, sq, off);
    }
    int wid = t >> 5, lid = t & 31;
    if (lid == 0) { red[wid] = s; red[wid + 32] = sq; }
    __syncthreads();
    __shared__ float mu_s, rstd_s;
    if (t == 0) {
        float S = 0.f, SQ = 0.f;
#pragma unroll
        for (int i = 0; i < 8; i++) { S += red[i]; SQ += red[i + 32]; }
        float mu = S * (1.f / D);
        float var = SQ * (1.f / D) - mu * mu;
        mu_s = mu;
        rstd_s = rsqrtf(var + 1e-5f);
    }
    __syncthreads();
    float mu = mu_s, r = rstd_s;
    ph[t]       = __float2half((x0 - mu) * r * g[t]       + b[t]);
    ph[t + 256] = __float2half((x1 - mu) * r * g[t + 256] + b[t + 256]);
    ph[t + 512] = __float2half((x2 - mu) * r * g[t + 512] + b[t + 512]);
}

// ---------------------------------------------------------------------------
extern "C" void kernel_launch(void* const* d_in, const int* in_sizes, int n_in,
                              void* d_out, int out_size)
{
    const float* x    = (const float*)d_in[0];
    const float* wq_p = (const float*)d_in[1];
    const float* wk_p = (const float*)d_in[2];
    const float* wv_p = (const float*)d_in[3];
    const float* wq_d = (const float*)d_in[4];
    const float* wk_d = (const float*)d_in[5];
    const float* wv_d = (const float*)d_in[6];
    const float* bq_p = (const float*)d_in[7];
    const float* bv_p = (const float*)d_in[8];
    const float* bq_d = (const float*)d_in[9];
    const float* bv_d = (const float*)d_in[10];
    const float* ln_g = (const float*)d_in[11];
    const float* ln_b = (const float*)d_in[12];
    const float* wo_p = (const float*)d_in[13];
    const float* bo_p = (const float*)d_in[14];
    const float* wo_d = (const float*)d_in[15];
    const float* bo_d = (const float*)d_in[16];
    float* out = (float*)d_out;

    __half *xh, *wh, *q, *k, *v, *oh;
    float *o;
    cudaGetSymbolAddress((void**)&xh, g_xh);
    cudaGetSymbolAddress((void**)&wh, g_wh);
    cudaGetSymbolAddress((void**)&q, g_q);
    cudaGetSymbolAddress((void**)&k, g_k);
    cudaGetSymbolAddress((void**)&v, g_v);
    cudaGetSymbolAddress((void**)&o, g_o);
    cudaGetSymbolAddress((void**)&oh, g_oh);

    cudaFuncSetAttribute(attn_tc, cudaFuncAttributeMaxDynamicSharedMemorySize, ATT_SMEM);

    // fp32 -> fp16 pre-passes
    const int nx = N_TOK * D;
    f2h_x<<<(nx / 8 + 255) / 256, 256>>>(x, xh, nx);
    dim3 gw(WSZ / 8 / 256, 8);
    w2h<<<gw, 256>>>(wq_p, wq_d, wk_p, wk_d, wv_p, wv_d, wo_p, wo_d, wh);

    // Fused QKV projections (fp16 tensor cores; q in log2 domain)
    dim3 gq(D / 128, 34, 3);
    qkv_gemm<<<gq, 256>>>(xh, wh, bq_p, bq_d, bv_p, bv_d, q, k, v);

    // Attention (fp16 flash, max-free exp2 softmax)
    dim3 ga((N_TOK + 127) / 128, H);
    attn_tc<<<ga, 256, ATT_SMEM>>>(q, k, v, o);

    // LayerNorm -> fp16
    ln_kernel<<<N_TOK, 256>>>(o, oh, ln_g, ln_b);

    // Output projection (fp16 tensor cores, fp32 out)
    dim3 go(D / 128, 34);
    out_gemm<<<go, 256>>>(oh, wh, bo_p, bo_d, out);
}

// round 17
// speedup vs baseline: 1.5357x; 1.5357x over previous
#include <cuda_runtime.h>
#include <cuda_fp16.h>
#include <math.h>

#define N_TOK 4301
#define NP    4201
#define ND    100
#define D     768
#define H     12
#define HD    64
// attention scores are produced in log2 domain: fold log2(e) into q scale
#define QSCALE_LOG2 (0.125f * 1.4426950408889634f)
#define WSZ   (D * D)

// Scratch (allocation-free rule: __device__ globals)
__device__ __half g_xh[(size_t)N_TOK * D];
__device__ __half g_wh[(size_t)8 * WSZ];     // 0=wq_p 1=wq_d 2=wk_p 3=wk_d 4=wv_p 5=wv_d 6=wo_p 7=wo_d
__device__ __half g_q[(size_t)N_TOK * D];
__device__ __half g_k[(size_t)N_TOK * D];
__device__ __half g_v[(size_t)N_TOK * D];
__device__ float  g_o[(size_t)N_TOK * D];
__device__ __half g_oh[(size_t)N_TOK * D];

// ---------------------------------------------------------------------------
// helpers
// ---------------------------------------------------------------------------
__device__ __forceinline__ void mma_f16(float* c,
    unsigned a0, unsigned a1, unsigned a2, unsigned a3,
    unsigned b0, unsigned b1)
{
    asm volatile(
        "mma.sync.aligned.m16n8k16.row.col.f32.f16.f16.f32 "
        "{%0,%1,%2,%3}, {%4,%5,%6,%7}, {%8,%9}, {%0,%1,%2,%3};"
        : "+f"(c[0]), "+f"(c[1]), "+f"(c[2]), "+f"(c[3])
        : "r"(a0), "r"(a1), "r"(a2), "r"(a3), "r"(b0), "r"(b1));
}
__device__ __forceinline__ void ldsm_x4(unsigned& r0, unsigned& r1,
                                        unsigned& r2, unsigned& r3, unsigned addr)
{
    asm volatile("ldmatrix.sync.aligned.m8n8.x4.shared.b16 {%0,%1,%2,%3}, [%4];"
                 : "=r"(r0), "=r"(r1), "=r"(r2), "=r"(r3) : "r"(addr));
}
__device__ __forceinline__ void ldsm_x4_t(unsigned& r0, unsigned& r1,
                                          unsigned& r2, unsigned& r3, unsigned addr)
{
    asm volatile("ldmatrix.sync.aligned.m8n8.x4.trans.shared.b16 {%0,%1,%2,%3}, [%4];"
                 : "=r"(r0), "=r"(r1), "=r"(r2), "=r"(r3) : "r"(addr));
}
__device__ __forceinline__ unsigned packh2(float lo, float hi) {
    __half2 h = __floats2half2_rn(lo, hi);
    return *(unsigned*)&h;
}
__device__ __forceinline__ unsigned ex2h2(unsigned x) {
    unsigned r;
    asm("ex2.approx.f16x2 %0, %1;" : "=r"(r) : "r"(x));
    return r;
}
__device__ __forceinline__ void cp_async16(unsigned dst, const void* src, int srcsize) {
    asm volatile("cp.async.cg.shared.global [%0], [%1], 16, %2;"
                 :: "r"(dst), "l"(src), "r"(srcsize));
}
__device__ __forceinline__ void cp_commit() {
    asm volatile("cp.async.commit_group;");
}

// ---------------------------------------------------------------------------
// fp32 -> fp16 conversion pre-passes
// ---------------------------------------------------------------------------
__global__ void __launch_bounds__(256) f2h_x(
    const float* __restrict__ src, __half* __restrict__ dst, int n)
{
    int i = (blockIdx.x * 256 + threadIdx.x) * 8;
    if (i < n) {
        float4 v0 = *(const float4*)(src + i);
        float4 v1 = *(const float4*)(src + i + 4);
        __half2 h[4];
        h[0] = __floats2half2_rn(v0.x, v0.y);
        h[1] = __floats2half2_rn(v0.z, v0.w);
        h[2] = __floats2half2_rn(v1.x, v1.y);
        h[3] = __floats2half2_rn(v1.z, v1.w);
        *(uint4*)(dst + i) = *(uint4*)h;
    }
}

__global__ void __launch_bounds__(256) w2h(
    const float* __restrict__ w0, const float* __restrict__ w1,
    const float* __restrict__ w2, const float* __restrict__ w3,
    const float* __restrict__ w4, const float* __restrict__ w5,
    const float* __restrict__ w6, const float* __restrict__ w7,
    __half* __restrict__ dst)
{
    const float* src;
    switch (blockIdx.y) {
        case 0: src = w0; break; case 1: src = w1; break;
        case 2: src = w2; break; case 3: src = w3; break;
        case 4: src = w4; break; case 5: src = w5; break;
        case 6: src = w6; break; default: src = w7; break;
    }
    __half* d = dst + (size_t)blockIdx.y * WSZ;
    int i = (blockIdx.x * 256 + threadIdx.x) * 8;
    float4 v0 = *(const float4*)(src + i);
    float4 v1 = *(const float4*)(src + i + 4);
    __half2 h[4];
    h[0] = __floats2half2_rn(v0.x, v0.y);
    h[1] = __floats2half2_rn(v0.z, v0.w);
    h[2] = __floats2half2_rn(v1.x, v1.y);
    h[3] = __floats2half2_rn(v1.z, v1.w);
    *(uint4*)(d + i) = *(uint4*)h;
}

// ---------------------------------------------------------------------------
// fp16 GEMM tile body (R13, unchanged): C = (A @ W^T + bias) * scale
// ---------------------------------------------------------------------------
#define GNK (D / 32)
#define HS  40

struct GemmSmemH {
    __half A[2][128 * HS];
    __half B[2][128 * HS];
};

template <bool HALF_OUT>
__device__ __forceinline__ void gemm_body_h(
    const __half* __restrict__ A, const __half* __restrict__ W,
    const float* __restrict__ bias,
    float* __restrict__ Cf, __half* __restrict__ Ch,
    int m0, int n0, int M, float scale, GemmSmemH& s)
{
    const int tid = threadIdx.x;
    const int w = tid >> 5;
    const int l = tid & 31;
    const int g = l >> 2;
    const int t = l & 3;
    const int wm = (w >> 2) * 64;
    const int wn = (w & 3) * 32;

    int cr[2], cc[2];
#pragma unroll
    for (int it = 0; it < 2; it++) {
        int slot = tid + 256 * it;
        cr[it] = slot >> 2;
        cc[it] = (slot & 3) * 8;
    }
    unsigned au = (unsigned)__cvta_generic_to_shared(s.A);
    unsigned bu = (unsigned)__cvta_generic_to_shared(s.B);

#pragma unroll
    for (int it = 0; it < 2; it++) {
        int row = m0 + cr[it];
        int ok = (row < M) ? 16 : 0;
        cp_async16(au + (cr[it] * HS + cc[it]) * 2,
                   A + (size_t)(ok ? row : m0) * D + cc[it], ok);
        cp_async16(bu + (cr[it] * HS + cc[it]) * 2,
                   W + (size_t)(n0 + cr[it]) * D + cc[it], 16);
    }
    cp_commit();

    float acc[4][4][4];
#pragma unroll
    for (int i = 0; i < 4; i++)
#pragma unroll
        for (int j = 0; j < 4; j++)
#pragma unroll
            for (int r = 0; r < 4; r++) acc[i][j][r] = 0.f;

    const int la = (l & 15) * HS + ((l >> 4) & 1) * 8;
    const int lb = (((l >> 4) << 3) + (l & 7)) * HS + ((l >> 3) & 1) * 8;

    for (int ki = 0; ki < GNK; ki++) {
        asm volatile("cp.async.wait_group 0;");
        __syncthreads();
        const int buf = ki & 1;

        if (ki + 1 < GNK) {
            const int k0 = (ki + 1) * 32;
            const unsigned an = au + ((buf ^ 1) * 128 * HS) * 2;
            const unsigned bn = bu + ((buf ^ 1) * 128 * HS) * 2;
#pragma unroll
            for (int it = 0; it < 2; it++) {
                int row = m0 + cr[it];
                int ok = (row < M) ? 16 : 0;
                cp_async16(an + (cr[it] * HS + cc[it]) * 2,
                           A + (size_t)(ok ? row : m0) * D + k0 + cc[it], ok);
                cp_async16(bn + (cr[it] * HS + cc[it]) * 2,
                           W + (size_t)(n0 + cr[it]) * D + k0 + cc[it], 16);
            }
            cp_commit();
        }

        const unsigned ab = au + (buf * 128 * HS) * 2;
        const unsigned bb = bu + (buf * 128 * HS) * 2;
#pragma unroll
        for (int kk = 0; kk < 2; kk++) {
            unsigned a[4][4];
#pragma unroll
            for (int i = 0; i < 4; i++)
                ldsm_x4(a[i][0], a[i][1], a[i][2], a[i][3],
                        ab + ((wm + i * 16) * HS + kk * 16 + la) * 2);
#pragma unroll
            for (int j2 = 0; j2 < 2; j2++) {
                unsigned b0, b1, b2, b3;
                ldsm_x4(b0, b1, b2, b3,
                        bb + ((wn + j2 * 16) * HS + kk * 16 + lb) * 2);
#pragma unroll
                for (int i = 0; i < 4; i++) {
                    mma_f16(acc[i][2 * j2],     a[i][0], a[i][1], a[i][2], a[i][3], b0, b1);
                    mma_f16(acc[i][2 * j2 + 1], a[i][0], a[i][1], a[i][2], a[i][3], b2, b3);
                }
            }
        }
        __syncthreads();
    }

#pragma unroll
    for (int j = 0; j < 4; j++) {
        int c0 = n0 + wn + j * 8 + t * 2;
        float b0v = bias ? bias[c0] : 0.f;
        float b1v = bias ? bias[c0 + 1] : 0.f;
#pragma unroll
        for (int i = 0; i < 4; i++) {
            int r0 = m0 + wm + i * 16 + g;
            int r1 = r0 + 8;
            if (r0 < M) {
                float px = (acc[i][j][0] + b0v) * scale;
                float py = (acc[i][j][1] + b1v) * scale;
                if (HALF_OUT)
                    *(__half2*)(Ch + (size_t)r0 * D + c0) = __floats2half2_rn(px, py);
                else
                    *(float2*)(Cf + (size_t)r0 * D + c0) = make_float2(px, py);
            }
            if (r1 < M) {
                float px = (acc[i][j][2] + b0v) * scale;
                float py = (acc[i][j][3] + b1v) * scale;
                if (HALF_OUT)
                    *(__half2*)(Ch + (size_t)r1 * D + c0) = __floats2half2_rn(px, py);
                else
                    *(float2*)(Cf + (size_t)r1 * D + c0) = make_float2(px, py);
            }
        }
    }
}

// Fused QKV: grid (6, 34, 3). q is scaled into the log2 domain.
__global__ void __launch_bounds__(256, 2) qkv_gemm(
    const __half* __restrict__ x, const __half* __restrict__ wh,
    const float* __restrict__ bq_p, const float* __restrict__ bq_d,
    const float* __restrict__ bv_p, const float* __restrict__ bv_d,
    __half* __restrict__ q, __half* __restrict__ k, __half* __restrict__ v)
{
    __shared__ GemmSmemH s;
    const bool det = (blockIdx.y == gridDim.y - 1);
    const int m0 = det ? NP : blockIdx.y * 128;
    const int M  = det ? N_TOK : NP;
    const int z = blockIdx.z;

    int wsel;
    const float* bias;
    __half* C;
    float scale = 1.f;
    if (z == 0) {
        wsel = det ? 1 : 0; bias = det ? bq_d : bq_p; C = q; scale = QSCALE_LOG2;
    } else if (z == 1) {
        wsel = det ? 3 : 2; bias = nullptr; C = k;
    } else {
        wsel = det ? 5 : 4; bias = det ? bv_d : bv_p; C = v;
    }
    gemm_body_h<true>(x, wh + (size_t)wsel * WSZ, bias, nullptr, C,
                      m0, blockIdx.x * 128, M, scale, s);
}

__global__ void __launch_bounds__(256, 2) out_gemm(
    const __half* __restrict__ A, const __half* __restrict__ wh,
    const float* __restrict__ bo_p, const float* __restrict__ bo_d,
    float* __restrict__ C)
{
    __shared__ GemmSmemH s;
    const bool det = (blockIdx.y == gridDim.y - 1);
    const int m0 = det ? NP : blockIdx.y * 128;
    const int M  = det ? N_TOK : NP;
    gemm_body_h<false>(A, wh + (size_t)(det ? 7 : 6) * WSZ,
                       det ? bo_d : bo_p, C, nullptr,
                       m0, blockIdx.x * 128, M, 1.f, s);
}

// ---------------------------------------------------------------------------
// fp16 flash attention: R13 pipeline (K single-buffer, V double-buffer,
// two barriers per tile) with max-free exp2 softmax. P fragments are
// precomputed in a tight MUFU loop BEFORE the PV mma stream so the HMMAs
// issue dependency-free (R14's mistake corrected). Row sums via ones-mma.
// ---------------------------------------------------------------------------
#define KH 72
#define VH 72
#define NKT ((N_TOK + 63) / 64)
#define ATT_SMEM ((64 * KH + 2 * 64 * VH) * 2)

__global__ void __launch_bounds__(256, 2) attn_tc(
    const __half* __restrict__ q, const __half* __restrict__ k,
    const __half* __restrict__ v, float* __restrict__ o)
{
    extern __shared__ __half smh[];
    __half* Ks  = smh;                 // [64][KH] single buf
    __half* Vs0 = smh + 64 * KH;       // [2][64][VH]

    const int h = blockIdx.y;
    const int q0 = blockIdx.x * 128;
    const int tid = threadIdx.x;
    const int w = tid >> 5;
    const int l = tid & 31;
    const int g = l >> 2;
    const int t = l & 3;
    const int wq = w * 16;
    const size_t hoff = (size_t)h * HD;
    const unsigned ONE2 = 0x3C003C00u;   // half2(1, 1)

    int cr_[2], cc_[2];
#pragma unroll
    for (int it = 0; it < 2; it++) {
        int slot = tid + 256 * it;
        cr_[it] = slot >> 3;
        cc_[it] = (slot & 7) * 8;
    }
    unsigned ks_u = (unsigned)__cvta_generic_to_shared(Ks);
    unsigned vs_u = (unsigned)__cvta_generic_to_shared(Vs0);

    // prologue: prefetch K0 + V0 (tile 0 full)
#pragma unroll
    for (int it = 0; it < 2; it++) {
        cp_async16(ks_u + (cr_[it] * KH + cc_[it]) * 2,
                   k + (size_t)cr_[it] * D + hoff + cc_[it], 16);
        cp_async16(vs_u + (cr_[it] * VH + cc_[it]) * 2,
                   v + (size_t)cr_[it] * D + hoff + cc_[it], 16);
    }
    cp_commit();

    // Q a-frags in registers (log2-domain scaled)
    unsigned aq[4][4];
    {
        int gr0 = q0 + wq + g, gr1 = gr0 + 8;
        bool v0 = gr0 < N_TOK, v1 = gr1 < N_TOK;
        const __half* q0p = q + (size_t)gr0 * D + hoff;
        const __half* q1p = q + (size_t)gr1 * D + hoff;
#pragma unroll
        for (int s = 0; s < 4; s++) {
            int c0 = s * 16 + 2 * t;
            aq[s][0] = v0 ? *(const unsigned*)(q0p + c0) : 0u;
            aq[s][1] = v1 ? *(const unsigned*)(q1p + c0) : 0u;
            aq[s][2] = v0 ? *(const unsigned*)(q0p + c0 + 8) : 0u;
            aq[s][3] = v1 ? *(const unsigned*)(q1p + c0 + 8) : 0u;
        }
    }

    const int lk = (((l >> 4) << 3) + (l & 7)) * KH + ((l >> 3) & 1) * 8;
    const int lv = ((((l >> 3) & 1) << 3) + (l & 7)) * VH + ((l >> 4) << 3);

    float oacc[8][4];
#pragma unroll
    for (int n = 0; n < 8; n++)
#pragma unroll
        for (int r = 0; r < 4; r++) oacc[n][r] = 0.f;
    float lacc[4] = { 0.f, 0.f, 0.f, 0.f };

    for (int ti = 0; ti < NKT; ti++) {
        const int t0 = ti * 64;
        const int cnt = min(64, N_TOK - t0);
        const int buf = ti & 1;
        const unsigned vb_u = vs_u + buf * 64 * VH * 2;

        // wait for K[ti] + V[ti]
        asm volatile("cp.async.wait_group 0;");
        __syncthreads();

        // S = Q @ K^T (log2-domain scores, fp32 accum)
        float sc[8][4];
#pragma unroll
        for (int n = 0; n < 8; n++)
#pragma unroll
            for (int r = 0; r < 4; r++) sc[n][r] = 0.f;

#pragma unroll
        for (int s = 0; s < 4; s++) {
#pragma unroll
            for (int np = 0; np < 4; np++) {
                unsigned b0, b1, b2, b3;
                ldsm_x4(b0, b1, b2, b3,
                        ks_u + (np * 16 * KH + s * 16 + lk) * 2);
                mma_f16(sc[2 * np],     aq[s][0], aq[s][1], aq[s][2], aq[s][3], b0, b1);
                mma_f16(sc[2 * np + 1], aq[s][0], aq[s][1], aq[s][2], aq[s][3], b2, b3);
            }
        }

        // K consumed by all warps -> safe to overwrite with K[ti+1]
        __syncthreads();
        if (ti + 1 < NKT) {
            const int nt0 = t0 + 64;
            const int ncnt = min(64, N_TOK - nt0);
            const unsigned vb2 = vs_u + (buf ^ 1) * 64 * VH * 2;
#pragma unroll
            for (int it = 0; it < 2; it++) {
                int row = cr_[it], cc = cc_[it];
                int ok = (row < ncnt) ? 16 : 0;
                size_t off = (size_t)(nt0 + (ok ? row : 0)) * D + hoff + cc;
                cp_async16(ks_u + (row * KH + cc) * 2, k + off, ok);
                cp_async16(vb2 + (row * VH + cc) * 2, v + off, ok);
            }
            cp_commit();
        }

        // Mask padded keys (last tile only): exp2(-60) == 0 in fp16
        if (cnt < 64) {
#pragma unroll
            for (int n = 0; n < 8; n++) {
                int j0 = n * 8 + t * 2;
                if (j0 >= cnt)     { sc[n][0] = -60.f; sc[n][2] = -60.f; }
                if (j0 + 1 >= cnt) { sc[n][1] = -60.f; sc[n][3] = -60.f; }
            }
        }

        // P = exp2(S): ALL MUFUs issued in one tight loop (latencies overlap)
        unsigned P[4][4];
#pragma unroll
        for (int s = 0; s < 4; s++) {
            P[s][0] = ex2h2(packh2(sc[2 * s][0],     sc[2 * s][1]));
            P[s][1] = ex2h2(packh2(sc[2 * s][2],     sc[2 * s][3]));
            P[s][2] = ex2h2(packh2(sc[2 * s + 1][0], sc[2 * s + 1][1]));
            P[s][3] = ex2h2(packh2(sc[2 * s + 1][2], sc[2 * s + 1][3]));
        }

        // Row sums via ones-column mma, then dependency-free PV mma stream
#pragma unroll
        for (int s = 0; s < 4; s++)
            mma_f16(lacc, P[s][0], P[s][1], P[s][2], P[s][3], ONE2, ONE2);

#pragma unroll
        for (int s = 0; s < 4; s++) {
#pragma unroll
            for (int np = 0; np < 4; np++) {
                unsigned b0, b1, b2, b3;
                ldsm_x4_t(b0, b1, b2, b3,
                          vb_u + (s * 16 * VH + np * 16 + lv) * 2);
                mma_f16(oacc[2 * np],     P[s][0], P[s][1], P[s][2], P[s][3], b0, b1);
                mma_f16(oacc[2 * np + 1], P[s][0], P[s][1], P[s][2], P[s][3], b2, b3);
            }
        }
    }

    // Epilogue: lacc[0] = row g sum, lacc[2] = row g+8 sum
    float i0 = 1.f / lacc[0], i1 = 1.f / lacc[2];
    int gr0 = q0 + wq + g, gr1 = gr0 + 8;
#pragma unroll
    for (int n = 0; n < 8; n++) {
        int c = h * HD + n * 8 + t * 2;
        if (gr0 < N_TOK) {
            float2 p;
            p.x = oacc[n][0] * i0; p.y = oacc[n][1] * i0;
            *(float2*)(o + (size_t)gr0 * D + c) = p;
        }
        if (gr1 < N_TOK) {
            float2 p;
            p.x = oacc[n][2] * i1; p.y = oacc[n][3] * i1;
            *(float2*)(o + (size_t)gr1 * D + c) = p;
        }
    }
}

// ---------------------------------------------------------------------------
// LayerNorm: reads fp32 attention output, writes fp16 for the out-projection.
// ---------------------------------------------------------------------------
__global__ void __launch_bounds__(256) ln_kernel(
    const float* __restrict__ o, __half* __restrict__ oh,
    const float* __restrict__ g, const float* __restrict__ b)
{
    const int row = blockIdx.x;
    const float* p = o + (size_t)row * D;
    __half* ph = oh + (size_t)row * D;
    const int t = threadIdx.x;
    float x0 = p[t], x1 = p[t + 256], x2 = p[t + 512];
    float s = x0 + x1 + x2;
    float sq = x0 * x0 + x1 * x1 + x2 * x2;

    __shared__ float red[64];
#pragma unroll
    for (int off = 16; off > 0; off >>= 1) {
        s  += __shfl_down_sync(0xffffffffu, s, off);
        sq += __shfl_down_sync(0xffffffffu, sq, off);
    }
    int wid = t >> 5, lid = t & 31;
    if (lid == 0) { red[wid] = s; red[wid + 32] = sq; }
    __syncthreads();
    __shared__ float mu_s, rstd_s;
    if (t == 0) {
        float S = 0.f, SQ = 0.f;
#pragma unroll
        for (int i = 0; i < 8; i++) { S += red[i]; SQ += red[i + 32]; }
        float mu = S * (1.f / D);
        float var = SQ * (1.f / D) - mu * mu;
        mu_s = mu;
        rstd_s = rsqrtf(var + 1e-5f);
    }
    __syncthreads();
    float mu = mu_s, r = rstd_s;
    ph[t]       = __float2half((x0 - mu) * r * g[t]       + b[t]);
    ph[t + 256] = __float2half((x1 - mu) * r * g[t + 256] + b[t + 256]);
    ph[t + 512] = __float2half((x2 - mu) * r * g[t + 512] + b[t + 512]);
}

// ---------------------------------------------------------------------------
extern "C" void kernel_launch(void* const* d_in, const int* in_sizes, int n_in,
                              void* d_out, int out_size)
{
    const float* x    = (const float*)d_in[0];
    const float* wq_p = (const float*)d_in[1];
    const float* wk_p = (const float*)d_in[2];
    const float* wv_p = (const float*)d_in[3];
    const float* wq_d = (const float*)d_in[4];
    const float* wk_d = (const float*)d_in[5];
    const float* wv_d = (const float*)d_in[6];
    const float* bq_p = (const float*)d_in[7];
    const float* bv_p = (const float*)d_in[8];
    const float* bq_d = (const float*)d_in[9];
    const float* bv_d = (const float*)d_in[10];
    const float* ln_g = (const float*)d_in[11];
    const float* ln_b = (const float*)d_in[12];
    const float* wo_p = (const float*)d_in[13];
    const float* bo_p = (const float*)d_in[14];
    const float* wo_d = (const float*)d_in[15];
    const float* bo_d = (const float*)d_in[16];
    float* out = (float*)d_out;

    __half *xh, *wh, *q, *k, *v, *oh;
    float *o;
    cudaGetSymbolAddress((void**)&xh, g_xh);
    cudaGetSymbolAddress((void**)&wh, g_wh);
    cudaGetSymbolAddress((void**)&q, g_q);
    cudaGetSymbolAddress((void**)&k, g_k);
    cudaGetSymbolAddress((void**)&v, g_v);
    cudaGetSymbolAddress((void**)&o, g_o);
    cudaGetSymbolAddress((void**)&oh, g_oh);

    cudaFuncSetAttribute(attn_tc, cudaFuncAttributeMaxDynamicSharedMemorySize, ATT_SMEM);

    // fp32 -> fp16 pre-passes
    const int nx = N_TOK * D;
    f2h_x<<<(nx / 8 + 255) / 256, 256>>>(x, xh, nx);
    dim3 gw(WSZ / 8 / 256, 8);
    w2h<<<gw, 256>>>(wq_p, wq_d, wk_p, wk_d, wv_p, wv_d, wo_p, wo_d, wh);

    // Fused QKV projections (fp16 tensor cores; q in log2 domain)
    dim3 gq(D / 128, 34, 3);
    qkv_gemm<<<gq, 256>>>(xh, wh, bq_p, bq_d, bv_p, bv_d, q, k, v);

    // Attention (fp16 flash, max-free staged-exp2 softmax)
    dim3 ga((N_TOK + 127) / 128, H);
    attn_tc<<<ga, 256, ATT_SMEM>>>(q, k, v, o);

    // LayerNorm -> fp16
    ln_kernel<<<N_TOK, 256>>>(o, oh, ln_g, ln_b);

    // Output projection (fp16 tensor cores, fp32 out)
    dim3 go(D / 128, 34);
    out_gemm<<<go, 256>>>(oh, wh, bo_p, bo_d, out);
}